// round 1
// baseline (speedup 1.0000x reference)
#include <cuda_runtime.h>
#include <cstdint>

typedef unsigned long long ull;

#define BATCH 2
#define SEQ   2048
#define EMB   1024
#define HEADS 16
#define HDIM  64
#define MTOT  (BATCH*SEQ)   // 4096

// ---------------- scratch (no allocations allowed) ----------------
__device__ float g_q[MTOT*EMB];
__device__ float g_k[MTOT*EMB];
__device__ float g_v[MTOT*EMB];      // permuted [b,h,t,d]
__device__ float g_attn[MTOT*EMB];   // [b,t,h*64+d]
__device__ ull   g_qbits[BATCH*HEADS*SEQ];
__device__ ull   g_kbits[BATCH*HEADS*SEQ];

// ---------------- GEMM: C = A @ W^T + bias ----------------
// A: [M,K] row-major, W: [N,K] row-major, bias: [N]
// mode 0: C[m][n] row-major   mode 1: v-permute C[((b*H+h)*T+t)*64+d]
#define BM 128
#define BN 128
#define BK 16
#define PAD 4

__global__ __launch_bounds__(256, 2)
void gemm_bias_kernel(const float* __restrict__ A, const float* __restrict__ W,
                      const float* __restrict__ bias, float* __restrict__ C,
                      int M, int N, int K, int mode)
{
    __shared__ float As[BK][BM + PAD];
    __shared__ float Bs[BK][BN + PAD];

    const int tid = threadIdx.x;
    const int m0 = blockIdx.y * BM;
    const int n0 = blockIdx.x * BN;

    const int lr  = tid >> 2;         // 0..63
    const int lc4 = (tid & 3) * 4;    // 0,4,8,12

    const int tm = (tid >> 4) * 8;    // 0..120
    const int tn = (tid & 15) * 8;

    float acc[8][8];
#pragma unroll
    for (int i = 0; i < 8; i++)
#pragma unroll
        for (int j = 0; j < 8; j++) acc[i][j] = 0.f;

    for (int k0 = 0; k0 < K; k0 += BK) {
#pragma unroll
        for (int h = 0; h < 2; h++) {
            int row = lr + 64 * h;
            float4 av = *(const float4*)&A[(size_t)(m0 + row) * K + k0 + lc4];
            As[lc4 + 0][row] = av.x;
            As[lc4 + 1][row] = av.y;
            As[lc4 + 2][row] = av.z;
            As[lc4 + 3][row] = av.w;
            float4 bv = *(const float4*)&W[(size_t)(n0 + row) * K + k0 + lc4];
            Bs[lc4 + 0][row] = bv.x;
            Bs[lc4 + 1][row] = bv.y;
            Bs[lc4 + 2][row] = bv.z;
            Bs[lc4 + 3][row] = bv.w;
        }
        __syncthreads();

#pragma unroll
        for (int kk = 0; kk < BK; kk++) {
            float a[8], b[8];
            *(float4*)(a)     = *(const float4*)&As[kk][tm];
            *(float4*)(a + 4) = *(const float4*)&As[kk][tm + 4];
            *(float4*)(b)     = *(const float4*)&Bs[kk][tn];
            *(float4*)(b + 4) = *(const float4*)&Bs[kk][tn + 4];
#pragma unroll
            for (int i = 0; i < 8; i++)
#pragma unroll
                for (int j = 0; j < 8; j++) acc[i][j] += a[i] * b[j];
        }
        __syncthreads();
    }

    // epilogue: add bias, store (vectorized; tn..tn+7 never crosses a head boundary)
    float bv[8];
#pragma unroll
    for (int j = 0; j < 8; j++) bv[j] = __ldg(&bias[n0 + tn + j]);

#pragma unroll
    for (int i = 0; i < 8; i++) {
        int m = m0 + tm + i;
        float r[8];
#pragma unroll
        for (int j = 0; j < 8; j++) r[j] = acc[i][j] + bv[j];
        if (mode == 0) {
            float* p = &C[(size_t)m * N + n0 + tn];
            *(float4*)(p)     = *(float4*)(r);
            *(float4*)(p + 4) = *(float4*)(r + 4);
        } else {
            int b_ = m >> 11, t = m & 2047;
            int n = n0 + tn;
            int h = n >> 6, d = n & 63;
            float* p = &C[(((size_t)(b_ * HEADS + h)) * SEQ + t) * HDIM + d];
            *(float4*)(p)     = *(float4*)(r);
            *(float4*)(p + 4) = *(float4*)(r + 4);
        }
    }
}

// ---------------- spike pack: one warp per (bt,h), ballot 64 dims ----------------
__global__ void pack_kernel(const float* __restrict__ q, const float* __restrict__ k,
                            ull* __restrict__ qbits, ull* __restrict__ kbits)
{
    int w = (blockIdx.x * blockDim.x + threadIdx.x) >> 5;
    int lane = threadIdx.x & 31;
    if (w >= MTOT * HEADS) return;
    int bt = w >> 4;
    int h  = w & 15;
    int b_ = bt >> 11, t = bt & 2047;
    size_t src = (size_t)bt * EMB + h * HDIM;
    size_t dst = ((size_t)(b_ * HEADS + h)) * SEQ + t;

    unsigned lo = __ballot_sync(0xFFFFFFFFu, q[src + lane] >= 1.0f);
    unsigned hi = __ballot_sync(0xFFFFFFFFu, q[src + 32 + lane] >= 1.0f);
    if (lane == 0) qbits[dst] = ((ull)hi << 32) | lo;

    lo = __ballot_sync(0xFFFFFFFFu, k[src + lane] >= 1.0f);
    hi = __ballot_sync(0xFFFFFFFFu, k[src + 32 + lane] >= 1.0f);
    if (lane == 0) kbits[dst] = ((ull)hi << 32) | lo;
}

// ---------------- attention: popcount scores -> exp table -> single-pass softmax*V ----
// block: 64 queries x 64 dims for one (b,h); loop keys in tiles of 64
__global__ __launch_bounds__(256)
void attn_kernel(const ull* __restrict__ qbits, const ull* __restrict__ kbits,
                 const float* __restrict__ vp, float* __restrict__ out)
{
    __shared__ float ws[64][64];   // [k][q] softmax weights (unnormalized)
    __shared__ float vs[64][64];   // [k][d]
    __shared__ ull   qb[64];
    __shared__ ull   kb[64];
    __shared__ float table[72];
    __shared__ float den[64];
    __shared__ float denp[4][64];

    const int tid = threadIdx.x;
    const int bh = blockIdx.y;            // 0..31
    const int q0 = blockIdx.x * 64;
    const ull* qptr = qbits + (size_t)bh * SEQ + q0;
    const ull* kptr = kbits + (size_t)bh * SEQ;
    const float* vptr = vp + (size_t)bh * SEQ * HDIM;

    if (tid < 65) table[tid] = expf((float)tid * 0.125f);
    if (tid < 64) qb[tid] = qptr[tid];
    __syncthreads();

    float acc[4][4];
#pragma unroll
    for (int i = 0; i < 4; i++)
#pragma unroll
        for (int j = 0; j < 4; j++) acc[i][j] = 0.f;

    float dpart = 0.f;
    const int tm = (tid >> 4) << 2;   // q offset
    const int tn = (tid & 15) << 2;   // d offset
    const int dq  = tid & 63;         // den partial: column
    const int dk0 = (tid >> 6) * 16;  // den partial: k range

    for (int kt = 0; kt < SEQ; kt += 64) {
        if (tid < 64) kb[tid] = kptr[kt + tid];
        // load V tile [64k x 64d]
#pragma unroll
        for (int r = 0; r < 4; r++) {
            int flat = r * 1024 + tid * 4;
            int k = flat >> 6, d = flat & 63;
            *(float4*)&vs[k][d] = *(const float4*)&vptr[(size_t)(kt + k) * HDIM + d];
        }
        __syncthreads();
        // build weight tile
#pragma unroll
        for (int e = 0; e < 16; e++) {
            int flat = tid + e * 256;
            int k = flat >> 6, q = flat & 63;
            int c = __popcll(qb[q] & kb[k]);
            ws[k][q] = table[c];
        }
        __syncthreads();
        // denominator partials
#pragma unroll
        for (int kk = 0; kk < 16; kk++) dpart += ws[dk0 + kk][dq];
        // AV accumulate
#pragma unroll
        for (int kk = 0; kk < 64; kk++) {
            float a[4], b[4];
            *(float4*)a = *(const float4*)&ws[kk][tm];
            *(float4*)b = *(const float4*)&vs[kk][tn];
#pragma unroll
            for (int i = 0; i < 4; i++)
#pragma unroll
                for (int j = 0; j < 4; j++) acc[i][j] += a[i] * b[j];
        }
        __syncthreads();
    }

    denp[tid >> 6][tid & 63] = dpart;
    __syncthreads();
    if (tid < 64) den[tid] = denp[0][tid] + denp[1][tid] + denp[2][tid] + denp[3][tid];
    __syncthreads();

    const int b_ = bh >> 4, h = bh & 15;
#pragma unroll
    for (int i = 0; i < 4; i++) {
        int q = tm + i;
        float inv = 1.0f / den[q];
        float r[4];
#pragma unroll
        for (int j = 0; j < 4; j++) r[j] = acc[i][j] * inv;
        float* p = &out[(size_t)(b_ * SEQ + q0 + q) * EMB + h * HDIM + tn];
        *(float4*)p = *(float4*)r;
    }
}

// ---------------- launch ----------------
extern "C" void kernel_launch(void* const* d_in, const int* in_sizes, int n_in,
                              void* d_out, int out_size)
{
    const float* x  = (const float*)d_in[0];
    const float* Wq = (const float*)d_in[1];
    const float* bq = (const float*)d_in[2];
    const float* Wk = (const float*)d_in[3];
    const float* bk = (const float*)d_in[4];
    const float* Wv = (const float*)d_in[5];
    const float* bv = (const float*)d_in[6];
    const float* Wo = (const float*)d_in[7];
    const float* bo = (const float*)d_in[8];
    float* out = (float*)d_out;

    float *gq, *gk, *gv, *ga;
    ull *gqb, *gkb;
    cudaGetSymbolAddress((void**)&gq,  g_q);
    cudaGetSymbolAddress((void**)&gk,  g_k);
    cudaGetSymbolAddress((void**)&gv,  g_v);
    cudaGetSymbolAddress((void**)&ga,  g_attn);
    cudaGetSymbolAddress((void**)&gqb, g_qbits);
    cudaGetSymbolAddress((void**)&gkb, g_kbits);

    dim3 gg(EMB / BN, MTOT / BM);   // (8, 32)

    gemm_bias_kernel<<<gg, 256>>>(x, Wq, bq, gq, MTOT, EMB, EMB, 0);
    gemm_bias_kernel<<<gg, 256>>>(x, Wk, bk, gk, MTOT, EMB, EMB, 0);
    gemm_bias_kernel<<<gg, 256>>>(x, Wv, bv, gv, MTOT, EMB, EMB, 1);

    pack_kernel<<<(MTOT * HEADS * 32) / 256, 256>>>(gq, gk, gqb, gkb);

    attn_kernel<<<dim3(SEQ / 64, BATCH * HEADS), 256>>>(gqb, gkb, gv, ga);

    gemm_bias_kernel<<<gg, 256>>>(ga, Wo, bo, out, MTOT, EMB, EMB, 0);
}